// round 1
// baseline (speedup 1.0000x reference)
#include <cuda_runtime.h>
#include <cstdint>

#define Dn 1024
#define Vn 64
#define TMn 32
#define NTHREADS 256
#define KCHUNK 128
#define NCHUNKS (Dn / KCHUNK)
#define PTHRESH 1e-8f

// head_weight transposed into d-pair-major layout: g_wt[dp*64 + v] = (hw[v][2dp], hw[v][2dp+1])
__device__ __align__(16) float2 g_wt[(Dn / 2) * Vn];

__global__ void k_transpose_w(const float* __restrict__ hw) {
    int i = blockIdx.x * blockDim.x + threadIdx.x;   // 0 .. 32767
    if (i >= Vn * (Dn / 2)) return;
    int v  = i >> 9;      // 512 pairs per vocab row
    int dp = i & 511;
    float2 p;
    p.x = hw[v * Dn + 2 * dp];
    p.y = hw[v * Dn + 2 * dp + 1];
    g_wt[dp * Vn + v] = p;
}

__device__ __forceinline__ unsigned long long ffma2(unsigned long long a,
                                                    unsigned long long b,
                                                    unsigned long long c) {
    unsigned long long d;
    asm("fma.rn.f32x2 %0, %1, %2, %3;" : "=l"(d) : "l"(a), "l"(b), "l"(c));
    return d;
}
__device__ __forceinline__ float f2lo(unsigned long long a) { return __uint_as_float((unsigned)a); }
__device__ __forceinline__ float f2hi(unsigned long long a) { return __uint_as_float((unsigned)(a >> 32)); }

// sigmoid for |z| <~ 0.3 (gate scale 0.01): odd poly, max err < 5e-8; exact fallback for tails.
__device__ __forceinline__ float sigmoid_f(float z) {
    float z2 = z * z;
    float p = fmaf(z, fmaf(z2, fmaf(z2, 0.00208333333f, -0.0208333333f), 0.25f), 0.5f);
    if (fabsf(z) > 0.35f) p = 1.0f / (1.0f + __expf(-z));
    return p;
}

__global__ void __launch_bounds__(NTHREADS, 1)
k_fused(const float* __restrict__ xg, const int* __restrict__ iw,
        const float* __restrict__ emb, const float* __restrict__ gate,
        const float* __restrict__ sgate, float* __restrict__ out,
        int idx_off, int has_idx)
{
    extern __shared__ char smem_raw[];
    float2* ws  = (float2*)smem_raw;                          // 32 KB  W chunk [64 dp][64 v] pairs
    float*  x1s = (float*)(smem_raw + 32768);                 // 128 KB x1 tile [32][1024]
    float*  gts = (float*)(smem_raw + 32768 + 131072);        // 4 KB gate
    float*  sgs = gts + Dn;                                   // 4 KB soft_gate

    const int tid  = threadIdx.x;
    const int lane = tid & 31;
    const int w    = tid >> 5;
    const int t0   = blockIdx.x * TMn;

    for (int i = tid; i < Dn; i += NTHREADS) { gts[i] = gate[i]; sgs[i] = sgate[i]; }

    // idx dtype detection: int64 storage => all high words zero; int32 => random values 0..63.
    int oddnz = (iw[2 * tid + 1] != 0);
    int is32  = __syncthreads_or(oddnz);   // also fences the gate staging

    // ---------------- Phase A: gate blend, x1 into smem, soft-gate mean ----------------
    float sgv[4];
    #pragma unroll
    for (int j = 0; j < 4; j++) {
        const int tl = w * 4 + j;
        const int tg = t0 + tl;
        const float* xr = xg + (size_t)tg * Dn;
        float* xs = x1s + tl * Dn;
        float s = 0.f;
        #pragma unroll 8
        for (int k = 0; k < 32; k++) {
            int d = lane + 32 * k;
            float xv = xr[d];
            xs[d] = xv;                      // stash raw x (warp-private rows)
            s += sigmoid_f(xv * gts[d]);
        }
        #pragma unroll
        for (int o = 16; o; o >>= 1) s += __shfl_xor_sync(0xffffffffu, s, o);
        float g = s * (1.0f / 1024.0f);

        int it = is32 ? iw[tg] : iw[2 * tg];
        it = min(max(it, 0), Vn - 1);
        const float* er = emb + (size_t)it * Dn;

        float ss = 0.f;
        #pragma unroll 8
        for (int k = 0; k < 32; k++) {
            int d = lane + 32 * k;
            float xv = xs[d];
            float x1 = fmaf(er[d] - xv, g, xv);   // x*(1-g) + emb*g
            xs[d] = x1;
            ss += sigmoid_f(x1 * sgs[d]);
        }
        #pragma unroll
        for (int o = 16; o; o >>= 1) ss += __shfl_xor_sync(0xffffffffu, ss, o);
        sgv[j] = ss * (1.0f / 1024.0f);
    }

    // ---------------- Phase B: logits GEMM, fp32 via packed f32x2 FFMA ----------------
    // warp -> 4 tokens; lane -> vocab pair (2*lane, 2*lane+1); acc over d-pairs.
    unsigned long long acc[4][2];
    #pragma unroll
    for (int j = 0; j < 4; j++) { acc[j][0] = 0ull; acc[j][1] = 0ull; }

    const ulonglong2* wsv = (const ulonglong2*)ws;
    for (int kc = 0; kc < NCHUNKS; kc++) {
        __syncthreads();
        const float4* src = (const float4*)(g_wt + kc * (KCHUNK / 2) * Vn);
        float4* dst = (float4*)ws;
        #pragma unroll
        for (int i = 0; i < 8; i++) dst[tid + i * NTHREADS] = src[tid + i * NTHREADS];
        __syncthreads();

        const ulonglong2* xrow[4];
        #pragma unroll
        for (int j = 0; j < 4; j++)
            xrow[j] = (const ulonglong2*)(x1s + (w * 4 + j) * Dn + kc * KCHUNK);

        #pragma unroll 8
        for (int dp2 = 0; dp2 < 32; dp2++) {
            ulonglong2 wa = wsv[(2 * dp2) * 32 + lane];       // d-pair 2*dp2, v = 2l,2l+1
            ulonglong2 wb = wsv[(2 * dp2 + 1) * 32 + lane];   // d-pair 2*dp2+1
            #pragma unroll
            for (int j = 0; j < 4; j++) {
                ulonglong2 xj = xrow[j][dp2];                 // two d-pairs (broadcast LDS.128)
                acc[j][0] = ffma2(xj.x, wa.x, acc[j][0]);
                acc[j][1] = ffma2(xj.x, wa.y, acc[j][1]);
                acc[j][0] = ffma2(xj.y, wb.x, acc[j][0]);
                acc[j][1] = ffma2(xj.y, wb.y, acc[j][1]);
            }
        }
    }

    // ---------------- Phase C: argmax + peaked softmax (sparse support) ----------------
    float p0a[4], p1a[4];
    unsigned m0a[4], m1a[4];
    #pragma unroll
    for (int j = 0; j < 4; j++) {
        float l0 = f2lo(acc[j][0]) + f2hi(acc[j][0]);
        float l1 = f2lo(acc[j][1]) + f2hi(acc[j][1]);
        float m = l0; int mi = 2 * lane;
        if (l1 > m) { m = l1; mi = 2 * lane + 1; }
        #pragma unroll
        for (int o = 16; o; o >>= 1) {
            float om = __shfl_xor_sync(0xffffffffu, m, o);
            int  omi = __shfl_xor_sync(0xffffffffu, mi, o);
            if (om > m || (om == m && omi < mi)) { m = om; mi = omi; }   // first-index tie rule
        }
        float e0 = __expf(l0 - m), e1 = __expf(l1 - m);
        float den = e0 + e1;
        #pragma unroll
        for (int o = 16; o; o >>= 1) den += __shfl_xor_sync(0xffffffffu, den, o);
        float rd = 1.0f / den;
        float p0 = e0 * rd, p1 = e1 * rd;
        p0a[j] = p0; p1a[j] = p1;
        m0a[j] = __ballot_sync(0xffffffffu, p0 > PTHRESH);
        m1a[j] = __ballot_sync(0xffffffffu, p1 > PTHRESH);
        if (has_idx && lane == 0) out[(size_t)idx_off + (t0 + w * 4 + j)] = (float)mi;
    }

    // ---------------- Phase D: sparse soft_emb gather + final blend + store ----------------
    #pragma unroll
    for (int j = 0; j < 4; j++) {
        const int tl = w * 4 + j;
        const int tg = t0 + tl;
        const float sgj = sgv[j];
        const float* xs = x1s + tl * Dn;
        float* orow = out + (size_t)tg * Dn;
        for (int c = 0; c < 4; c++) {
            float av[8];
            #pragma unroll
            for (int i = 0; i < 8; i++) av[i] = 0.f;
            unsigned mm = m0a[j];
            while (mm) {                         // trip count uniform across warp (from ballot)
                int b = __ffs(mm) - 1; mm &= mm - 1;
                float p = __shfl_sync(0xffffffffu, p0a[j], b);
                const float* er = emb + (size_t)(2 * b) * Dn + c * 256 + lane;
                #pragma unroll
                for (int i = 0; i < 8; i++) av[i] = fmaf(p, __ldg(er + 32 * i), av[i]);
            }
            mm = m1a[j];
            while (mm) {
                int b = __ffs(mm) - 1; mm &= mm - 1;
                float p = __shfl_sync(0xffffffffu, p1a[j], b);
                const float* er = emb + (size_t)(2 * b + 1) * Dn + c * 256 + lane;
                #pragma unroll
                for (int i = 0; i < 8; i++) av[i] = fmaf(p, __ldg(er + 32 * i), av[i]);
            }
            #pragma unroll
            for (int i = 0; i < 8; i++) {
                int d = c * 256 + lane + 32 * i;
                float xv = xs[d];
                orow[d] = fmaf(sgj, av[i] - xv, xv);   // x1*(1-sg) + soft_emb*sg
            }
        }
    }
}

extern "C" void kernel_launch(void* const* d_in, const int* in_sizes, int n_in,
                              void* d_out, int out_size) {
    (void)n_in;
    const float* x     = (const float*)d_in[0];
    const int*   idx   = (const int*)d_in[1];
    const float* emb   = (const float*)d_in[2];
    const float* hw    = (const float*)d_in[3];
    const float* gate  = (const float*)d_in[4];
    const float* sgate = (const float*)d_in[5];
    float* out = (float*)d_out;

    const int n_tok   = in_sizes[0] / Dn;          // 32768
    const int idx_off = in_sizes[0];               // x-part element count
    const int has_idx = (out_size >= idx_off + n_tok) ? 1 : 0;

    const int smem_bytes = 32768 + TMn * Dn * 4 + 2 * Dn * 4;   // 172032
    cudaFuncSetAttribute(k_fused, cudaFuncAttributeMaxDynamicSharedMemorySize, smem_bytes);

    k_transpose_w<<<(Vn * (Dn / 2) + 255) / 256, 256>>>(hw);
    k_fused<<<n_tok / TMn, NTHREADS, smem_bytes>>>(x, idx, emb, gate, sgate, out,
                                                   idx_off, has_idx);
}